// round 5
// baseline (speedup 1.0000x reference)
#include <cuda_runtime.h>
#include <math_constants.h>
#include <cstdint>

#define BATCH   4
#define N_UP    16384
#define N_DOWN  4096
#define C_UP    384
#define C_DOWN  512
#define C_OUT   512
#define KNN     3
#define EPSW    1e-8f

#define M_UP   (BATCH * N_UP)     // 65536
#define M_DN   (BATCH * N_DOWN)   // 16384

// ---------------- scratch (__device__ globals; no allocs allowed) ----------
__device__ float g_down_f[M_DN * C_OUT];                 // 32 MB fp32
__device__ int   g_idx[M_UP * KNN];
__device__ float g_w[M_UP * KNN];

__device__ signed char g_a1_up[(size_t)M_UP * C_UP];
__device__ signed char g_a2_up[(size_t)M_UP * C_UP];
__device__ signed char g_b1_up[(size_t)C_OUT * C_UP];
__device__ signed char g_b2_up[(size_t)C_OUT * C_UP];
__device__ signed char g_a1_dn[(size_t)M_DN * C_DOWN];
__device__ signed char g_a2_dn[(size_t)M_DN * C_DOWN];
__device__ signed char g_b1_dn[(size_t)C_OUT * C_DOWN];
__device__ signed char g_b2_dn[(size_t)C_OUT * C_DOWN];
__device__ float g_sa_up[M_UP], g_sb_up[C_OUT];
__device__ float g_sa_dn[M_DN], g_sb_dn[C_OUT];

// ---------------- helpers ---------------------------------------------------
static __device__ __forceinline__ uint32_t smem_u32(const void* p) {
    uint32_t a;
    asm("{ .reg .u64 t; cvta.to.shared.u64 t, %1; cvt.u32.u64 %0, t; }"
        : "=r"(a) : "l"(p));
    return a;
}
static __device__ __forceinline__ void cp16(uint32_t dst, const void* src) {
    asm volatile("cp.async.cg.shared.global [%0], [%1], 16;"
                 :: "r"(dst), "l"(src) : "memory");
}
static __device__ __forceinline__ void cp_commit() {
    asm volatile("cp.async.commit_group;" ::: "memory");
}
static __device__ __forceinline__ void cp_wait2() {
    asm volatile("cp.async.wait_group 2;" ::: "memory");
}
static __device__ __forceinline__ void ldmx4(uint32_t& r0, uint32_t& r1,
                                             uint32_t& r2, uint32_t& r3,
                                             uint32_t addr) {
    asm volatile("ldmatrix.sync.aligned.m8n8.x4.shared.b16 {%0,%1,%2,%3}, [%4];"
                 : "=r"(r0), "=r"(r1), "=r"(r2), "=r"(r3) : "r"(addr));
}
static __device__ __forceinline__ void mma16832(int* c, const uint32_t* a,
                                                uint32_t b0, uint32_t b1) {
    asm volatile(
        "mma.sync.aligned.m16n8k32.row.col.s32.s8.s8.s32 "
        "{%0,%1,%2,%3}, {%4,%5,%6,%7}, {%8,%9}, {%0,%1,%2,%3};"
        : "+r"(c[0]), "+r"(c[1]), "+r"(c[2]), "+r"(c[3])
        : "r"(a[0]), "r"(a[1]), "r"(a[2]), "r"(a[3]), "r"(b0), "r"(b1));
}

// ---------------- dual-digit int8 quantization -----------------------------
// v = x / s, s = absmax*128/127 so |v| <= 127/128.
// a1 = rint(v*2^7); e = v - a1*2^-7 (|e| <= 2^-8); a2 = clamp(rint(e*2^15)).
// x ~= s * (a1*2^-7 + a2*2^-15), error ~ s*2^-16.
template<int K>
__global__ __launch_bounds__(256) void quant_rows(
    const float* __restrict__ x, signed char* __restrict__ q1,
    signed char* __restrict__ q2, float* __restrict__ sc, int M)
{
    constexpr int F4 = K / 128;    // float4 per lane (3 or 4)
    const int w = (blockIdx.x * 256 + threadIdx.x) >> 5;
    const int lane = threadIdx.x & 31;
    if (w >= M) return;
    const float4* row = (const float4*)(x + (size_t)w * K);
    float4 v[F4];
    float am = 0.0f;
#pragma unroll
    for (int i = 0; i < F4; i++) {
        v[i] = row[lane + 32 * i];
        am = fmaxf(am, fmaxf(fmaxf(fabsf(v[i].x), fabsf(v[i].y)),
                             fmaxf(fabsf(v[i].z), fabsf(v[i].w))));
    }
#pragma unroll
    for (int off = 16; off > 0; off >>= 1)
        am = fmaxf(am, __shfl_xor_sync(0xffffffffu, am, off));
    const float s = fmaxf(am, 1e-30f) * (128.0f / 127.0f);
    const float inv = 1.0f / s;
    if (lane == 0) sc[w] = s;

    char4* o1 = (char4*)(q1 + (size_t)w * K);
    char4* o2 = (char4*)(q2 + (size_t)w * K);
#pragma unroll
    for (int i = 0; i < F4; i++) {
        float t[4] = { v[i].x * inv, v[i].y * inv, v[i].z * inv, v[i].w * inv };
        char d1[4], d2[4];
#pragma unroll
        for (int e = 0; e < 4; e++) {
            float q1f = rintf(t[e] * 128.0f);
            q1f = fminf(127.0f, fmaxf(-127.0f, q1f));
            float r = fmaf(q1f, -0.0078125f, t[e]);          // t - q1/128
            float q2f = rintf(r * 32768.0f);
            q2f = fminf(127.0f, fmaxf(-127.0f, q2f));
            d1[e] = (char)(int)q1f;
            d2[e] = (char)(int)q2f;
        }
        o1[lane + 32 * i] = make_char4(d1[0], d1[1], d1[2], d1[3]);
        o2[lane + 32 * i] = make_char4(d2[0], d2[1], d2[2], d2[3]);
    }
}

// ---------------------------------------------------------------------------
// int8 dual-digit GEMM: out[m,n] = s_a[m]*s_b[n]*2^-14*acc + bias[n] (+interp)
// Segment order: seg1 (A1*B2), seg2 (A2*B1) -> acc; acc = (acc+128)>>8;
// seg0 (A1*B1) -> acc. CTA 128x128, BK=64 int8, 4-stage cp.async, 8 warps,
// warp tile 64x32, m16n8k32.s8.
// ---------------------------------------------------------------------------
#define SM_STAGE 20480            // (128 rows * 80B) * 2 (A+B)
template<int K, bool FUSED>
__global__ __launch_bounds__(256, 2) void gemm_i8(
    const signed char* __restrict__ A1, const signed char* __restrict__ A2,
    const signed char* __restrict__ B1, const signed char* __restrict__ B2,
    const float* __restrict__ sa, const float* __restrict__ sb,
    const float* __restrict__ bias, float* __restrict__ outp)
{
    constexpr int SEGC = K / 64;
    constexpr int NC = 3 * SEGC;
    extern __shared__ __align__(16) char smt[];
    const uint32_t sbase = smem_u32(smt);

    const int tid = threadIdx.x;
    const int lane = tid & 31;
    const int wid = tid >> 5;
    const int wm = wid >> 2;        // 0..1 -> m offset wm*64
    const int wn = wid & 3;         // 0..3 -> n offset wn*32
    const int m0 = blockIdx.y * 128;
    const int n0 = blockIdx.x * 128;

    // cp.async slots: thread covers rows (row, row+64), 16B chunk q
    const int row = tid >> 2;
    const int q = tid & 3;

    // ldmatrix per-lane offsets (byte units)
    const int lq = lane >> 3, l7 = lane & 7;
    const int aRow = (lq & 1) * 8 + l7, aKb = (lq >> 1) * 16;
    const int bRow = (lq >> 1) * 8 + l7, bKb = (lq & 1) * 16;

    int acc[4][4][4];
#pragma unroll
    for (int i = 0; i < 4; i++)
#pragma unroll
        for (int j = 0; j < 4; j++)
#pragma unroll
            for (int r = 0; r < 4; r++) acc[i][j][r] = 0;

    auto issue = [&](int c) {
        if (c < NC) {
            const int seg = c / SEGC;               // 0: A1B2, 1: A2B1, 2: A1B1
            const int kk = (c - seg * SEGC) * 64;
            const signed char* As = (seg == 1) ? A2 : A1;
            const signed char* Bs = (seg == 0) ? B2 : B1;
            const signed char* srcA = As + (size_t)(m0 + row) * K + kk + q * 16;
            const signed char* srcB = Bs + (size_t)(n0 + row) * K + kk + q * 16;
            uint32_t dA = sbase + (c & 3) * SM_STAGE + row * 80 + q * 16;
            uint32_t dB = dA + 10240;
            cp16(dA, srcA);
            cp16(dA + 64 * 80, srcA + (size_t)64 * K);
            cp16(dB, srcB);
            cp16(dB + 64 * 80, srcB + (size_t)64 * K);
        }
        cp_commit();
    };

    issue(0); issue(1); issue(2);

    for (int c = 0; c < NC; c++) {
        cp_wait2();
        __syncthreads();
        issue(c + 3);                 // overwrites stage (c-1)&3: safe past sync

        if (c == 2 * SEGC) {          // cross phase done: fold 2^-22 -> 2^-14
#pragma unroll
            for (int i = 0; i < 4; i++)
#pragma unroll
                for (int j = 0; j < 4; j++)
#pragma unroll
                    for (int r = 0; r < 4; r++)
                        acc[i][j][r] = (acc[i][j][r] + 128) >> 8;
        }

        const uint32_t sA = sbase + (c & 3) * SM_STAGE;
        const uint32_t sB = sA + 10240;
#pragma unroll
        for (int ks = 0; ks < 2; ks++) {
            uint32_t a[4][4];
#pragma unroll
            for (int i = 0; i < 4; i++) {
                uint32_t addr = sA + (uint32_t)(wm * 64 + i * 16 + aRow) * 80
                              + ks * 32 + aKb;
                ldmx4(a[i][0], a[i][1], a[i][2], a[i][3], addr);
            }
            uint32_t b[4][2];
#pragma unroll
            for (int jp = 0; jp < 2; jp++) {
                uint32_t addr = sB + (uint32_t)(wn * 32 + jp * 16 + bRow) * 80
                              + ks * 32 + bKb;
                ldmx4(b[jp * 2][0], b[jp * 2][1], b[jp * 2 + 1][0], b[jp * 2 + 1][1], addr);
            }
#pragma unroll
            for (int i = 0; i < 4; i++)
#pragma unroll
                for (int j = 0; j < 4; j++)
                    mma16832(acc[i][j], a[i], b[j][0], b[j][1]);
        }
    }

    // final fold: if loop ended exactly at boundary? (NC = 3*SEGC > 2*SEGC, so
    // fold already happened inside the loop for all K >= 64.)

    // ---------------- epilogue ----------------
    const float C_F = 6.103515625e-05f;   // 2^-14
    float* obase = FUSED ? outp : g_down_f;
#pragma unroll
    for (int i = 0; i < 4; i++) {
        const int r0 = m0 + wm * 64 + i * 16 + (lane >> 2);
        const int r1 = r0 + 8;
        const float sa0 = sa[r0] * C_F;
        const float sa1 = sa[r1] * C_F;
        const float* df0 = nullptr; const float* df1 = nullptr;
        int i00=0,i01=0,i02=0, i10=0,i11=0,i12=0;
        float w00=0,w01=0,w02=0, w10=0,w11=0,w12=0;
        if (FUSED) {
            df0 = g_down_f + (size_t)(r0 >> 14) * N_DOWN * C_OUT;
            df1 = g_down_f + (size_t)(r1 >> 14) * N_DOWN * C_OUT;
            int ib0 = r0 * KNN, ib1 = r1 * KNN;
            i00 = g_idx[ib0]; i01 = g_idx[ib0+1]; i02 = g_idx[ib0+2];
            w00 = g_w[ib0];   w01 = g_w[ib0+1];   w02 = g_w[ib0+2];
            i10 = g_idx[ib1]; i11 = g_idx[ib1+1]; i12 = g_idx[ib1+2];
            w10 = g_w[ib1];   w11 = g_w[ib1+1];   w12 = g_w[ib1+2];
        }
#pragma unroll
        for (int j = 0; j < 4; j++) {
            const int n = n0 + wn * 32 + j * 8 + (lane & 3) * 2;
            const float2 bi  = *(const float2*)(bias + n);
            const float2 sbv = *(const float2*)(sb + n);
            float2 o0, o1;
            o0.x = fmaf(sa0 * sbv.x, __int2float_rn(acc[i][j][0]), bi.x);
            o0.y = fmaf(sa0 * sbv.y, __int2float_rn(acc[i][j][1]), bi.y);
            o1.x = fmaf(sa1 * sbv.x, __int2float_rn(acc[i][j][2]), bi.x);
            o1.y = fmaf(sa1 * sbv.y, __int2float_rn(acc[i][j][3]), bi.y);
            if (FUSED) {
                float2 a0 = *(const float2*)(df0 + (size_t)i00 * C_OUT + n);
                float2 a1v = *(const float2*)(df0 + (size_t)i01 * C_OUT + n);
                float2 a2v = *(const float2*)(df0 + (size_t)i02 * C_OUT + n);
                o0.x += w00 * a0.x + w01 * a1v.x + w02 * a2v.x;
                o0.y += w00 * a0.y + w01 * a1v.y + w02 * a2v.y;
                float2 c0 = *(const float2*)(df1 + (size_t)i10 * C_OUT + n);
                float2 c1 = *(const float2*)(df1 + (size_t)i11 * C_OUT + n);
                float2 c2 = *(const float2*)(df1 + (size_t)i12 * C_OUT + n);
                o1.x += w10 * c0.x + w11 * c1.x + w12 * c2.x;
                o1.y += w10 * c0.y + w11 * c1.y + w12 * c2.y;
            }
            *(float2*)(obase + (size_t)r0 * C_OUT + n) = o0;
            *(float2*)(obase + (size_t)r1 * C_OUT + n) = o1;
        }
    }
}

// ---------------------------------------------------------------------------
// KNN (unchanged): rank by t = d2 - 2*dot; strict-< insertion for stability.
// ---------------------------------------------------------------------------
__global__ __launch_bounds__(256) void knn_kernel(
    const float* __restrict__ up_points,
    const float* __restrict__ down_points)
{
    __shared__ float4 sp[2048];

    const int b = blockIdx.y;
    const int n = blockIdx.x * 256 + threadIdx.x;

    const float* up = up_points + (size_t)(b * N_UP + n) * 3;
    const float ux = up[0], uy = up[1], uz = up[2];
    const float u2 = ux * ux + uy * uy + uz * uz;
    const float a0 = -2.0f * ux, a1 = -2.0f * uy, a2 = -2.0f * uz;

    float bd0 = CUDART_INF_F, bd1 = CUDART_INF_F, bd2 = CUDART_INF_F;
    int   bi0 = 0, bi1 = 0, bi2 = 0;

    for (int phase = 0; phase < 2; phase++) {
        const int mbase = phase * 2048;
        __syncthreads();
        for (int i = threadIdx.x; i < 2048; i += 256) {
            const float* dp = down_points + (size_t)(b * N_DOWN + mbase + i) * 3;
            float x = dp[0], y = dp[1], z = dp[2];
            sp[i] = make_float4(x, y, z, x * x + y * y + z * z);
        }
        __syncthreads();

        for (int m = 0; m < 2048; m += 8) {
            float t[8];
#pragma unroll
            for (int j = 0; j < 8; j++) {
                float4 p = sp[m + j];
                t[j] = fmaf(a0, p.x, fmaf(a1, p.y, fmaf(a2, p.z, p.w)));
            }
            float mn = fminf(fminf(fminf(t[0], t[1]), fminf(t[2], t[3])),
                             fminf(fminf(t[4], t[5]), fminf(t[6], t[7])));
            if (mn < bd2) {
#pragma unroll
                for (int j = 0; j < 8; j++) {
                    float d = t[j];
                    if (d < bd2) {
                        int mi = mbase + m + j;
                        if (d < bd1) {
                            bd2 = bd1; bi2 = bi1;
                            if (d < bd0) { bd1 = bd0; bi1 = bi0; bd0 = d; bi0 = mi; }
                            else          { bd1 = d;  bi1 = mi; }
                        } else {
                            bd2 = d; bi2 = mi;
                        }
                    }
                }
            }
        }
    }

    float d0 = bd0 + u2, d1 = bd1 + u2, d2 = bd2 + u2;
    float w0 = 1.0f / (d0 + EPSW);
    float w1 = 1.0f / (d1 + EPSW);
    float w2 = 1.0f / (d2 + EPSW);
    float inv = 1.0f / (w0 + w1 + w2);

    const int base = (b * N_UP + n) * KNN;
    g_idx[base + 0] = bi0; g_idx[base + 1] = bi1; g_idx[base + 2] = bi2;
    g_w[base + 0] = w0 * inv; g_w[base + 1] = w1 * inv; g_w[base + 2] = w2 * inv;
}

// ---------------------------------------------------------------------------
extern "C" void kernel_launch(void* const* d_in, const int* in_sizes, int n_in,
                              void* d_out, int out_size) {
    (void)in_sizes; (void)n_in; (void)out_size;
    const float* up_points     = (const float*)d_in[0];
    const float* up_features   = (const float*)d_in[1];
    const float* down_points   = (const float*)d_in[2];
    const float* down_features = (const float*)d_in[3];
    const float* W_up          = (const float*)d_in[4];
    const float* b_up          = (const float*)d_in[5];
    const float* W_down        = (const float*)d_in[6];
    const float* b_down        = (const float*)d_in[7];
    float* out = (float*)d_out;

    void *a1u, *a2u, *b1u, *b2u, *a1d, *a2d, *b1d, *b2d;
    void *sau, *sbu, *sad, *sbd;
    cudaGetSymbolAddress(&a1u, g_a1_up);  cudaGetSymbolAddress(&a2u, g_a2_up);
    cudaGetSymbolAddress(&b1u, g_b1_up);  cudaGetSymbolAddress(&b2u, g_b2_up);
    cudaGetSymbolAddress(&a1d, g_a1_dn);  cudaGetSymbolAddress(&a2d, g_a2_dn);
    cudaGetSymbolAddress(&b1d, g_b1_dn);  cudaGetSymbolAddress(&b2d, g_b2_dn);
    cudaGetSymbolAddress(&sau, g_sa_up);  cudaGetSymbolAddress(&sbu, g_sb_up);
    cudaGetSymbolAddress(&sad, g_sa_dn);  cudaGetSymbolAddress(&sbd, g_sb_dn);

    static bool attr_done = false;
    if (!attr_done) {
        cudaFuncSetAttribute(gemm_i8<C_DOWN, false>,
                             cudaFuncAttributeMaxDynamicSharedMemorySize, 4 * SM_STAGE);
        cudaFuncSetAttribute(gemm_i8<C_UP, true>,
                             cudaFuncAttributeMaxDynamicSharedMemorySize, 4 * SM_STAGE);
        attr_done = true;
    }

    // quantization (8 rows per 256-thread block)
    quant_rows<C_UP><<<M_UP / 8, 256>>>(up_features, (signed char*)a1u,
                                        (signed char*)a2u, (float*)sau, M_UP);
    quant_rows<C_UP><<<C_OUT / 8, 256>>>(W_up, (signed char*)b1u,
                                         (signed char*)b2u, (float*)sbu, C_OUT);
    quant_rows<C_DOWN><<<M_DN / 8, 256>>>(down_features, (signed char*)a1d,
                                          (signed char*)a2d, (float*)sad, M_DN);
    quant_rows<C_DOWN><<<C_OUT / 8, 256>>>(W_down, (signed char*)b1d,
                                           (signed char*)b2d, (float*)sbd, C_OUT);

    dim3 gk(N_UP / 256, BATCH);
    knn_kernel<<<gk, 256>>>(up_points, down_points);

    dim3 g1(C_OUT / 128, M_DN / 128);   // (4, 128)
    gemm_i8<C_DOWN, false><<<g1, 256, 4 * SM_STAGE>>>(
        (const signed char*)a1d, (const signed char*)a2d,
        (const signed char*)b1d, (const signed char*)b2d,
        (const float*)sad, (const float*)sbd, b_down, nullptr);

    dim3 g2(C_OUT / 128, M_UP / 128);   // (4, 512)
    gemm_i8<C_UP, true><<<g2, 256, 4 * SM_STAGE>>>(
        (const signed char*)a1u, (const signed char*)a2u,
        (const signed char*)b1u, (const signed char*)b2u,
        (const float*)sau, (const float*)sbu, b_up, out);
}

// round 6
// speedup vs baseline: 1.6080x; 1.6080x over previous
#include <cuda_runtime.h>
#include <math_constants.h>
#include <cstdint>

#define BATCH   4
#define N_UP    16384
#define N_DOWN  4096
#define C_UP    384
#define C_DOWN  512
#define C_OUT   512
#define KNN     3
#define EPSW    1e-8f

#define M_UP   (BATCH * N_UP)     // 65536
#define M_DN   (BATCH * N_DOWN)   // 16384

// ---------------- scratch (__device__ globals; no allocs allowed) ----------
__device__ float g_down_f[M_DN * C_OUT];                 // 32 MB fp32
__device__ int   g_idx[M_UP * KNN];
__device__ float g_w[M_UP * KNN];

__device__ unsigned short g_Ah_up[(size_t)M_UP * C_UP];
__device__ unsigned short g_Al_up[(size_t)M_UP * C_UP];
__device__ unsigned short g_Wh_up[(size_t)C_OUT * C_UP];
__device__ unsigned short g_Wl_up[(size_t)C_OUT * C_UP];
__device__ unsigned short g_Ah_dn[(size_t)M_DN * C_DOWN];
__device__ unsigned short g_Al_dn[(size_t)M_DN * C_DOWN];
__device__ unsigned short g_Wh_dn[(size_t)C_OUT * C_DOWN];
__device__ unsigned short g_Wl_dn[(size_t)C_OUT * C_DOWN];

// ---------------- helpers ---------------------------------------------------
static __device__ __forceinline__ uint32_t smem_u32(const void* p) {
    uint32_t a;
    asm("{ .reg .u64 t; cvta.to.shared.u64 t, %1; cvt.u32.u64 %0, t; }"
        : "=r"(a) : "l"(p));
    return a;
}
static __device__ __forceinline__ unsigned short f2bf(float f) {
    unsigned short u;
    asm("cvt.rn.bf16.f32 %0, %1;" : "=h"(u) : "f"(f));
    return u;
}
static __device__ __forceinline__ float bf2f(unsigned short u) {
    return __uint_as_float(((uint32_t)u) << 16);
}
static __device__ __forceinline__ void cp16(uint32_t dst, const void* src) {
    asm volatile("cp.async.cg.shared.global [%0], [%1], 16;"
                 :: "r"(dst), "l"(src) : "memory");
}
static __device__ __forceinline__ void cp_commit() {
    asm volatile("cp.async.commit_group;" ::: "memory");
}
static __device__ __forceinline__ void cp_wait2() {
    asm volatile("cp.async.wait_group 2;" ::: "memory");
}
static __device__ __forceinline__ void ldmx4(uint32_t& r0, uint32_t& r1,
                                             uint32_t& r2, uint32_t& r3,
                                             uint32_t addr) {
    asm volatile("ldmatrix.sync.aligned.m8n8.x4.shared.b16 {%0,%1,%2,%3}, [%4];"
                 : "=r"(r0), "=r"(r1), "=r"(r2), "=r"(r3) : "r"(addr));
}
static __device__ __forceinline__ void mma16816(float* c, const uint32_t* a,
                                                uint32_t b0, uint32_t b1) {
    asm volatile(
        "mma.sync.aligned.m16n8k16.row.col.f32.bf16.bf16.f32 "
        "{%0,%1,%2,%3}, {%4,%5,%6,%7}, {%8,%9}, {%0,%1,%2,%3};"
        : "+f"(c[0]), "+f"(c[1]), "+f"(c[2]), "+f"(c[3])
        : "r"(a[0]), "r"(a[1]), "r"(a[2]), "r"(a[3]), "r"(b0), "r"(b1));
}

// ---------------- hi/lo bf16 split -----------------------------------------
__global__ __launch_bounds__(256) void conv_hilo(
    const float4* __restrict__ x, ushort4* __restrict__ h4,
    ushort4* __restrict__ l4, int n4)
{
    int i = blockIdx.x * 256 + threadIdx.x;
    if (i >= n4) return;
    float4 v = x[i];
    ushort4 h, l;
    h.x = f2bf(v.x); l.x = f2bf(v.x - bf2f(h.x));
    h.y = f2bf(v.y); l.y = f2bf(v.y - bf2f(h.y));
    h.z = f2bf(v.z); l.z = f2bf(v.z - bf2f(h.z));
    h.w = f2bf(v.w); l.w = f2bf(v.w - bf2f(h.w));
    h4[i] = h; l4[i] = l;
}

// ---------------------------------------------------------------------------
// bf16 hi/lo GEMM via mma.sync: out[m,n] = sum_k A[m,k]*Wt[n,k] + bias[n]
// (+ KNN interpolation when FUSED). Effective K' = 3K via segments:
//   seg0: Ah*Bh   seg1: Ah*Bl   seg2: Al*Bh
// CTA 128x128, BK=32 bf16, 4-stage cp.async ring (1 sync/chunk), 8 warps,
// warp tile 64x32, m16n8k16.
// ---------------------------------------------------------------------------
#define SM_STAGE 20480            // (128 rows * 80B) * 2 (A+B)
template<int K, bool FUSED>
__global__ __launch_bounds__(256) void gemm_bf16(
    const unsigned short* __restrict__ Ah, const unsigned short* __restrict__ Al,
    const unsigned short* __restrict__ Bh, const unsigned short* __restrict__ Bl,
    const float* __restrict__ bias, float* __restrict__ outp)
{
    constexpr int SEGC = K / 32;
    constexpr int NC = 3 * SEGC;
    extern __shared__ __align__(16) char smt[];
    const uint32_t sbase = smem_u32(smt);

    const int tid = threadIdx.x;
    const int lane = tid & 31;
    const int wid = tid >> 5;
    const int wm = wid >> 2;        // 0..1 -> m offset wm*64
    const int wn = wid & 3;         // 0..3 -> n offset wn*32
    const int m0 = blockIdx.y * 128;
    const int n0 = blockIdx.x * 128;

    // cp.async slots: thread covers rows (row, row+64), 16B chunk q
    const int row = tid >> 2;
    const int q = tid & 3;

    // ldmatrix per-lane offsets
    const int lq = lane >> 3, l7 = lane & 7;
    const int aRow = (lq & 1) * 8 + l7, aK = (lq >> 1) * 8;
    const int bRow = (lq >> 1) * 8 + l7, bK = (lq & 1) * 8;

    float acc[4][4][4];
#pragma unroll
    for (int i = 0; i < 4; i++)
#pragma unroll
        for (int j = 0; j < 4; j++)
#pragma unroll
            for (int r = 0; r < 4; r++) acc[i][j][r] = 0.0f;

    auto issue = [&](int c) {
        if (c < NC) {
            const int seg = c / SEGC;
            const int kk = (c - seg * SEGC) * 32;
            const unsigned short* As = (seg < 2) ? Ah : Al;
            const unsigned short* Bs = (seg == 1) ? Bl : Bh;
            const unsigned short* srcA = As + (size_t)(m0 + row) * K + kk + q * 8;
            const unsigned short* srcB = Bs + (size_t)(n0 + row) * K + kk + q * 8;
            uint32_t dA = sbase + (c & 3) * SM_STAGE + row * 80 + q * 16;
            uint32_t dB = dA + 10240;
            cp16(dA, srcA);
            cp16(dA + 64 * 80, srcA + (size_t)64 * K);
            cp16(dB, srcB);
            cp16(dB + 64 * 80, srcB + (size_t)64 * K);
        }
        cp_commit();
    };

    issue(0); issue(1); issue(2);

    for (int c = 0; c < NC; c++) {
        cp_wait2();
        __syncthreads();
        issue(c + 3);                 // overwrites stage (c-1)&3: safe past sync

        const uint32_t sA = sbase + (c & 3) * SM_STAGE;
        const uint32_t sB = sA + 10240;
#pragma unroll
        for (int ks = 0; ks < 2; ks++) {
            uint32_t a[4][4];
#pragma unroll
            for (int i = 0; i < 4; i++) {
                uint32_t addr = sA + (uint32_t)(wm * 64 + i * 16 + aRow) * 80
                              + (uint32_t)(ks * 16 + aK) * 2;
                ldmx4(a[i][0], a[i][1], a[i][2], a[i][3], addr);
            }
            uint32_t b[4][2];
#pragma unroll
            for (int jp = 0; jp < 2; jp++) {
                uint32_t addr = sB + (uint32_t)(wn * 32 + jp * 16 + bRow) * 80
                              + (uint32_t)(ks * 16 + bK) * 2;
                ldmx4(b[jp * 2][0], b[jp * 2][1], b[jp * 2 + 1][0], b[jp * 2 + 1][1], addr);
            }
#pragma unroll
            for (int i = 0; i < 4; i++)
#pragma unroll
                for (int j = 0; j < 4; j++)
                    mma16816(acc[i][j], a[i], b[j][0], b[j][1]);
        }
    }

    // ---------------- epilogue ----------------
    float* obase = FUSED ? outp : g_down_f;
#pragma unroll
    for (int i = 0; i < 4; i++) {
        const int r0 = m0 + wm * 64 + i * 16 + (lane >> 2);
        const int r1 = r0 + 8;
        const float* df0 = nullptr; const float* df1 = nullptr;
        int i00=0,i01=0,i02=0, i10=0,i11=0,i12=0;
        float w00=0,w01=0,w02=0, w10=0,w11=0,w12=0;
        if (FUSED) {
            df0 = g_down_f + (size_t)(r0 >> 14) * N_DOWN * C_OUT;
            df1 = g_down_f + (size_t)(r1 >> 14) * N_DOWN * C_OUT;
            int ib0 = r0 * KNN, ib1 = r1 * KNN;
            i00 = g_idx[ib0]; i01 = g_idx[ib0+1]; i02 = g_idx[ib0+2];
            w00 = g_w[ib0];   w01 = g_w[ib0+1];   w02 = g_w[ib0+2];
            i10 = g_idx[ib1]; i11 = g_idx[ib1+1]; i12 = g_idx[ib1+2];
            w10 = g_w[ib1];   w11 = g_w[ib1+1];   w12 = g_w[ib1+2];
        }
#pragma unroll
        for (int j = 0; j < 4; j++) {
            const int n = n0 + wn * 32 + j * 8 + (lane & 3) * 2;
            const float2 bi = *(const float2*)(bias + n);
            float2 o0, o1;
            o0.x = acc[i][j][0] + bi.x;  o0.y = acc[i][j][1] + bi.y;
            o1.x = acc[i][j][2] + bi.x;  o1.y = acc[i][j][3] + bi.y;
            if (FUSED) {
                float2 a0 = *(const float2*)(df0 + (size_t)i00 * C_OUT + n);
                float2 a1 = *(const float2*)(df0 + (size_t)i01 * C_OUT + n);
                float2 a2 = *(const float2*)(df0 + (size_t)i02 * C_OUT + n);
                o0.x += w00 * a0.x + w01 * a1.x + w02 * a2.x;
                o0.y += w00 * a0.y + w01 * a1.y + w02 * a2.y;
                float2 c0 = *(const float2*)(df1 + (size_t)i10 * C_OUT + n);
                float2 c1 = *(const float2*)(df1 + (size_t)i11 * C_OUT + n);
                float2 c2 = *(const float2*)(df1 + (size_t)i12 * C_OUT + n);
                o1.x += w10 * c0.x + w11 * c1.x + w12 * c2.x;
                o1.y += w10 * c0.y + w11 * c1.y + w12 * c2.y;
            }
            *(float2*)(obase + (size_t)r0 * C_OUT + n) = o0;
            *(float2*)(obase + (size_t)r1 * C_OUT + n) = o1;
        }
    }
}

// ---------------------------------------------------------------------------
// KNN: rank by t = d2 - 2*dot; strict-< insertion for stability.
// ---------------------------------------------------------------------------
__global__ __launch_bounds__(256) void knn_kernel(
    const float* __restrict__ up_points,
    const float* __restrict__ down_points)
{
    __shared__ float4 sp[2048];

    const int b = blockIdx.y;
    const int n = blockIdx.x * 256 + threadIdx.x;

    const float* up = up_points + (size_t)(b * N_UP + n) * 3;
    const float ux = up[0], uy = up[1], uz = up[2];
    const float u2 = ux * ux + uy * uy + uz * uz;
    const float a0 = -2.0f * ux, a1 = -2.0f * uy, a2 = -2.0f * uz;

    float bd0 = CUDART_INF_F, bd1 = CUDART_INF_F, bd2 = CUDART_INF_F;
    int   bi0 = 0, bi1 = 0, bi2 = 0;

    for (int phase = 0; phase < 2; phase++) {
        const int mbase = phase * 2048;
        __syncthreads();
        for (int i = threadIdx.x; i < 2048; i += 256) {
            const float* dp = down_points + (size_t)(b * N_DOWN + mbase + i) * 3;
            float x = dp[0], y = dp[1], z = dp[2];
            sp[i] = make_float4(x, y, z, x * x + y * y + z * z);
        }
        __syncthreads();

        for (int m = 0; m < 2048; m += 8) {
            float t[8];
#pragma unroll
            for (int j = 0; j < 8; j++) {
                float4 p = sp[m + j];
                t[j] = fmaf(a0, p.x, fmaf(a1, p.y, fmaf(a2, p.z, p.w)));
            }
            float mn = fminf(fminf(fminf(t[0], t[1]), fminf(t[2], t[3])),
                             fminf(fminf(t[4], t[5]), fminf(t[6], t[7])));
            if (mn < bd2) {
#pragma unroll
                for (int j = 0; j < 8; j++) {
                    float d = t[j];
                    if (d < bd2) {
                        int mi = mbase + m + j;
                        if (d < bd1) {
                            bd2 = bd1; bi2 = bi1;
                            if (d < bd0) { bd1 = bd0; bi1 = bi0; bd0 = d; bi0 = mi; }
                            else          { bd1 = d;  bi1 = mi; }
                        } else {
                            bd2 = d; bi2 = mi;
                        }
                    }
                }
            }
        }
    }

    float d0 = bd0 + u2, d1 = bd1 + u2, d2 = bd2 + u2;
    float w0 = 1.0f / (d0 + EPSW);
    float w1 = 1.0f / (d1 + EPSW);
    float w2 = 1.0f / (d2 + EPSW);
    float inv = 1.0f / (w0 + w1 + w2);

    const int base = (b * N_UP + n) * KNN;
    g_idx[base + 0] = bi0; g_idx[base + 1] = bi1; g_idx[base + 2] = bi2;
    g_w[base + 0] = w0 * inv; g_w[base + 1] = w1 * inv; g_w[base + 2] = w2 * inv;
}

// ---------------------------------------------------------------------------
extern "C" void kernel_launch(void* const* d_in, const int* in_sizes, int n_in,
                              void* d_out, int out_size) {
    (void)in_sizes; (void)n_in; (void)out_size;
    const float* up_points     = (const float*)d_in[0];
    const float* up_features   = (const float*)d_in[1];
    const float* down_points   = (const float*)d_in[2];
    const float* down_features = (const float*)d_in[3];
    const float* W_up          = (const float*)d_in[4];
    const float* b_up          = (const float*)d_in[5];
    const float* W_down        = (const float*)d_in[6];
    const float* b_down        = (const float*)d_in[7];
    float* out = (float*)d_out;

    void *pAhU, *pAlU, *pWhU, *pWlU, *pAhD, *pAlD, *pWhD, *pWlD;
    cudaGetSymbolAddress(&pAhU, g_Ah_up);
    cudaGetSymbolAddress(&pAlU, g_Al_up);
    cudaGetSymbolAddress(&pWhU, g_Wh_up);
    cudaGetSymbolAddress(&pWlU, g_Wl_up);
    cudaGetSymbolAddress(&pAhD, g_Ah_dn);
    cudaGetSymbolAddress(&pAlD, g_Al_dn);
    cudaGetSymbolAddress(&pWhD, g_Wh_dn);
    cudaGetSymbolAddress(&pWlD, g_Wl_dn);

    cudaFuncSetAttribute(gemm_bf16<C_DOWN, false>,
                         cudaFuncAttributeMaxDynamicSharedMemorySize, 4 * SM_STAGE);
    cudaFuncSetAttribute(gemm_bf16<C_UP, true>,
                         cudaFuncAttributeMaxDynamicSharedMemorySize, 4 * SM_STAGE);

    // hi/lo splits
    {
        int n4 = M_UP * C_UP / 4;
        conv_hilo<<<(n4 + 255) / 256, 256>>>((const float4*)up_features,
                                             (ushort4*)pAhU, (ushort4*)pAlU, n4);
    }
    {
        int n4 = C_OUT * C_UP / 4;
        conv_hilo<<<(n4 + 255) / 256, 256>>>((const float4*)W_up,
                                             (ushort4*)pWhU, (ushort4*)pWlU, n4);
    }
    {
        int n4 = M_DN * C_DOWN / 4;
        conv_hilo<<<(n4 + 255) / 256, 256>>>((const float4*)down_features,
                                             (ushort4*)pAhD, (ushort4*)pAlD, n4);
    }
    {
        int n4 = C_OUT * C_DOWN / 4;
        conv_hilo<<<(n4 + 255) / 256, 256>>>((const float4*)W_down,
                                             (ushort4*)pWhD, (ushort4*)pWlD, n4);
    }

    dim3 gk(N_UP / 256, BATCH);
    knn_kernel<<<gk, 256>>>(up_points, down_points);

    dim3 g1(C_OUT / 128, M_DN / 128);   // (4, 128)
    gemm_bf16<C_DOWN, false><<<g1, 256, 4 * SM_STAGE>>>(
        (const unsigned short*)pAhD, (const unsigned short*)pAlD,
        (const unsigned short*)pWhD, (const unsigned short*)pWlD,
        b_down, nullptr);

    dim3 g2(C_OUT / 128, M_UP / 128);   // (4, 512)
    gemm_bf16<C_UP, true><<<g2, 256, 4 * SM_STAGE>>>(
        (const unsigned short*)pAhU, (const unsigned short*)pAlU,
        (const unsigned short*)pWhU, (const unsigned short*)pWlU,
        b_up, out);
}